// round 11
// baseline (speedup 1.0000x reference)
#include <cuda_runtime.h>
#include <cuda_bf16.h>
#include <stdint.h>

#define BATCH 4096
#define NCLS  50257
#define EPSV  1e-12f

// Scratch + completion counter (no device allocation allowed -> __device__ globals)
__device__ float g_row_loss[BATCH];
__device__ unsigned int g_done = 0;

__device__ __forceinline__ float stable_s(float x) {
    // x >= 0 ? x + 1 : 1/(1-x)
    float p = x + 1.0f;
    float n = 1.0f - x;
    float r = __fdividef(1.0f, n);   // MUFU.RCP path (~1e-6 rel err)
    return (x >= 0.0f) ? p : r;
}

__device__ __forceinline__ float s4(float4 v) {
    return (stable_s(v.x) + stable_s(v.y)) + (stable_s(v.z) + stable_s(v.w));
}

// Re-entrant block reduction (leading barrier protects smem reuse across calls).
__device__ __forceinline__ float block_reduce_sum(float v) {
    __shared__ float warp_sums[8];
    int lane = threadIdx.x & 31;
    int wid  = threadIdx.x >> 5;
    __syncthreads();
    #pragma unroll
    for (int off = 16; off > 0; off >>= 1)
        v += __shfl_xor_sync(0xffffffffu, v, off);
    if (lane == 0) warp_sums[wid] = v;
    __syncthreads();
    v = (threadIdx.x < 8) ? warp_sums[threadIdx.x] : 0.0f;
    if (wid == 0) {
        #pragma unroll
        for (int off = 4; off > 0; off >>= 1)
            v += __shfl_xor_sync(0xffffffffu, v, off);
    }
    return v;  // valid in thread 0
}

__global__ void __launch_bounds__(256, 2)
stablemax_fused_kernel(const float* __restrict__ logits,
                       const int* __restrict__ targets,
                       float* __restrict__ out) {
    const int row = blockIdx.x;
    const float* __restrict__ rp = logits + (size_t)row * NCLS;
    const int stride = 256;

    // Hoist the target index load so its DRAM latency overlaps the main body.
    int tgt = 0;
    if (threadIdx.x == 0) {
        tgt = __ldg(&targets[row]);
        tgt = min(max(tgt, 0), NCLS - 1);   // fail-soft on dtype surprises
    }

    float acc0 = 0.f, acc1 = 0.f, acc2 = 0.f, acc3 = 0.f,
          acc4 = 0.f, acc5 = 0.f, acc6 = 0.f, acc7 = 0.f;

    // Scalar prefix until 16B alignment (row base only 4B aligned: NCLS odd)
    int prefix = (int)(((16u - ((uintptr_t)rp & 15u)) & 15u) >> 2);
    if (prefix > NCLS) prefix = NCLS;
    for (int j = threadIdx.x; j < prefix; j += stride)
        acc0 += stable_s(rp[j]);

    // 16x unrolled main body: 16 independent LDG.128 front-batched per
    // iteration (8 KB burst/warp). Measured trend: bigger per-warp bursts ->
    // higher average outstanding bytes -> higher DRAM% (76.5 @4x, 82.5 @8x).
    const int n4 = (NCLS - prefix) >> 2;
    const float4* __restrict__ rp4 = (const float4*)(rp + prefix);
    int j = threadIdx.x;
    for (; j + 15 * stride < n4; j += 16 * stride) {
        float4 v0  = rp4[j];
        float4 v1  = rp4[j +      stride];
        float4 v2  = rp4[j +  2 * stride];
        float4 v3  = rp4[j +  3 * stride];
        float4 v4  = rp4[j +  4 * stride];
        float4 v5  = rp4[j +  5 * stride];
        float4 v6  = rp4[j +  6 * stride];
        float4 v7  = rp4[j +  7 * stride];
        float4 v8  = rp4[j +  8 * stride];
        float4 v9  = rp4[j +  9 * stride];
        float4 v10 = rp4[j + 10 * stride];
        float4 v11 = rp4[j + 11 * stride];
        float4 v12 = rp4[j + 12 * stride];
        float4 v13 = rp4[j + 13 * stride];
        float4 v14 = rp4[j + 14 * stride];
        float4 v15 = rp4[j + 15 * stride];
        acc0 += s4(v0);
        acc1 += s4(v1);
        acc2 += s4(v2);
        acc3 += s4(v3);
        acc4 += s4(v4);
        acc5 += s4(v5);
        acc6 += s4(v6);
        acc7 += s4(v7);
        acc0 += s4(v8);
        acc1 += s4(v9);
        acc2 += s4(v10);
        acc3 += s4(v11);
        acc4 += s4(v12);
        acc5 += s4(v13);
        acc6 += s4(v14);
        acc7 += s4(v15);
    }
    // 4x-unrolled cleanup
    for (; j + 3 * stride < n4; j += 4 * stride) {
        float4 v0 = rp4[j];
        float4 v1 = rp4[j +     stride];
        float4 v2 = rp4[j + 2 * stride];
        float4 v3 = rp4[j + 3 * stride];
        acc0 += s4(v0);
        acc1 += s4(v1);
        acc2 += s4(v2);
        acc3 += s4(v3);
    }
    for (; j < n4; j += stride)
        acc0 += s4(rp4[j]);

    // Scalar tail (at most 3 elements)
    for (int t = prefix + (n4 << 2) + threadIdx.x; t < NCLS; t += stride)
        acc1 += stable_s(rp[t]);

    // Dependent target-logit load issued before the block reduction so its
    // latency hides under the barriers + shuffle tree.
    float st = 0.0f;
    if (threadIdx.x == 0)
        st = stable_s(__ldg(&rp[tgt]));

    float denom = block_reduce_sum(((acc0 + acc1) + (acc2 + acc3)) +
                                   ((acc4 + acc5) + (acc6 + acc7)));

    __shared__ bool is_last;
    if (threadIdx.x == 0) {
        denom = fmaxf(denom, EPSV);
        float pt = fmaxf(__fdividef(st, denom), EPSV);
        g_row_loss[row] = -__logf(pt);
        __threadfence();                         // publish row loss (release)
        unsigned int done = atomicAdd(&g_done, 1u);
        is_last = (done == (unsigned int)(BATCH - 1));
    }
    __syncthreads();

    if (is_last) {
        // Deterministic mean: fixed-order tree over g_row_loss.
        // 4096 floats = 1024 float4; 256 threads -> 4 float4 each, fixed indices.
        const float4* __restrict__ rl4 = (const float4*)g_row_loss;
        float acc = 0.0f;
        #pragma unroll
        for (int k = 0; k < 4; k++) {
            float4 v = __ldcg(&rl4[threadIdx.x + k * 256]);  // L2-coherent read
            acc += (v.x + v.y) + (v.z + v.w);
        }
        float total = block_reduce_sum(acc);
        if (threadIdx.x == 0) {
            out[0] = total * (1.0f / (float)BATCH);
            g_done = 0;                          // reset for next graph replay
        }
    }
}

extern "C" void kernel_launch(void* const* d_in, const int* in_sizes, int n_in,
                              void* d_out, int out_size) {
    const float* logits  = (const float*)d_in[0];
    const int*   targets = (const int*)d_in[1];
    float*       out     = (float*)d_out;
    (void)in_sizes; (void)n_in; (void)out_size;

    stablemax_fused_kernel<<<BATCH, 256>>>(logits, targets, out);
}

// round 12
// speedup vs baseline: 1.0444x; 1.0444x over previous
#include <cuda_runtime.h>
#include <cuda_bf16.h>
#include <stdint.h>

#define BATCH 4096
#define NCLS  50257
#define EPSV  1e-12f

// Scratch + completion counter (no device allocation allowed -> __device__ globals)
__device__ float g_row_loss[BATCH];
__device__ unsigned int g_done = 0;

__device__ __forceinline__ float stable_s(float x) {
    // x >= 0 ? x + 1 : 1/(1-x)
    float p = x + 1.0f;
    float n = 1.0f - x;
    float r = __fdividef(1.0f, n);   // MUFU.RCP path (~1e-6 rel err)
    return (x >= 0.0f) ? p : r;
}

__device__ __forceinline__ float s4(float4 v) {
    return (stable_s(v.x) + stable_s(v.y)) + (stable_s(v.z) + stable_s(v.w));
}

// Re-entrant block reduction (leading barrier protects smem reuse across calls).
__device__ __forceinline__ float block_reduce_sum(float v) {
    __shared__ float warp_sums[8];
    int lane = threadIdx.x & 31;
    int wid  = threadIdx.x >> 5;
    __syncthreads();
    #pragma unroll
    for (int off = 16; off > 0; off >>= 1)
        v += __shfl_xor_sync(0xffffffffu, v, off);
    if (lane == 0) warp_sums[wid] = v;
    __syncthreads();
    v = (threadIdx.x < 8) ? warp_sums[threadIdx.x] : 0.0f;
    if (wid == 0) {
        #pragma unroll
        for (int off = 4; off > 0; off >>= 1)
            v += __shfl_xor_sync(0xffffffffu, v, off);
    }
    return v;  // valid in thread 0
}

__global__ void __launch_bounds__(256, 2)
stablemax_fused_kernel(const float* __restrict__ logits,
                       const int* __restrict__ targets,
                       float* __restrict__ out) {
    const int row = blockIdx.x;
    const float* __restrict__ rp = logits + (size_t)row * NCLS;
    const int stride = 256;

    // Hoist the target index load so its DRAM latency overlaps the main body.
    int tgt = 0;
    if (threadIdx.x == 0) {
        tgt = __ldg(&targets[row]);
        tgt = min(max(tgt, 0), NCLS - 1);   // fail-soft on dtype surprises
    }

    float acc0 = 0.f, acc1 = 0.f, acc2 = 0.f, acc3 = 0.f,
          acc4 = 0.f, acc5 = 0.f, acc6 = 0.f, acc7 = 0.f;

    // Scalar prefix until 16B alignment (row base only 4B aligned: NCLS odd)
    int prefix = (int)(((16u - ((uintptr_t)rp & 15u)) & 15u) >> 2);
    if (prefix > NCLS) prefix = NCLS;
    for (int j = threadIdx.x; j < prefix; j += stride)
        acc0 += stable_s(rp[j]);

    // Software-pipelined 8x main body: the NEXT batch's 8 LDG.128 are issued
    // before the CURRENT batch is consumed, so each warp keeps ~8 loads in
    // flight through its compute phase (duty cycle ~100% vs ~50% plain 8x).
    // Measured: plain 8x = DRAM 82.5%; bursty 16x regressed (71.6%, occ 25%).
    const int n4 = (NCLS - prefix) >> 2;
    const float4* __restrict__ rp4 = (const float4*)(rp + prefix);
    const int last = n4 - 7 * stride;   // full batch exists iff j < last

    int j = threadIdx.x;
    float4 cur0, cur1, cur2, cur3, cur4, cur5, cur6, cur7;
    bool have = (j < last);
    if (have) {
        cur0 = rp4[j];
        cur1 = rp4[j +     stride];
        cur2 = rp4[j + 2 * stride];
        cur3 = rp4[j + 3 * stride];
        cur4 = rp4[j + 4 * stride];
        cur5 = rp4[j + 5 * stride];
        cur6 = rp4[j + 6 * stride];
        cur7 = rp4[j + 7 * stride];
        j += 8 * stride;
    }
    while (j < last) {
        // Prefetch next batch (8 independent LDG.128 front-batched)
        float4 n0 = rp4[j];
        float4 n1 = rp4[j +     stride];
        float4 n2 = rp4[j + 2 * stride];
        float4 n3 = rp4[j + 3 * stride];
        float4 n4v = rp4[j + 4 * stride];
        float4 n5 = rp4[j + 5 * stride];
        float4 n6 = rp4[j + 6 * stride];
        float4 n7 = rp4[j + 7 * stride];
        // Consume current batch while the prefetch is in flight
        acc0 += s4(cur0);
        acc1 += s4(cur1);
        acc2 += s4(cur2);
        acc3 += s4(cur3);
        acc4 += s4(cur4);
        acc5 += s4(cur5);
        acc6 += s4(cur6);
        acc7 += s4(cur7);
        cur0 = n0; cur1 = n1; cur2 = n2; cur3 = n3;
        cur4 = n4v; cur5 = n5; cur6 = n6; cur7 = n7;
        j += 8 * stride;
    }
    if (have) {
        acc0 += s4(cur0);
        acc1 += s4(cur1);
        acc2 += s4(cur2);
        acc3 += s4(cur3);
        acc4 += s4(cur4);
        acc5 += s4(cur5);
        acc6 += s4(cur6);
        acc7 += s4(cur7);
    }
    // Remainder float4s (fewer than a full batch)
    for (; j < n4; j += stride)
        acc0 += s4(rp4[j]);

    // Scalar tail (at most 3 elements)
    for (int t = prefix + (n4 << 2) + threadIdx.x; t < NCLS; t += stride)
        acc1 += stable_s(rp[t]);

    // Dependent target-logit load issued before the block reduction so its
    // latency hides under the barriers + shuffle tree.
    float st = 0.0f;
    if (threadIdx.x == 0)
        st = stable_s(__ldg(&rp[tgt]));

    float denom = block_reduce_sum(((acc0 + acc1) + (acc2 + acc3)) +
                                   ((acc4 + acc5) + (acc6 + acc7)));

    __shared__ bool is_last;
    if (threadIdx.x == 0) {
        denom = fmaxf(denom, EPSV);
        float pt = fmaxf(__fdividef(st, denom), EPSV);
        g_row_loss[row] = -__logf(pt);
        __threadfence();                         // publish row loss (release)
        unsigned int done = atomicAdd(&g_done, 1u);
        is_last = (done == (unsigned int)(BATCH - 1));
    }
    __syncthreads();

    if (is_last) {
        // Deterministic mean: fixed-order tree over g_row_loss.
        // 4096 floats = 1024 float4; 256 threads -> 4 float4 each, fixed indices.
        const float4* __restrict__ rl4 = (const float4*)g_row_loss;
        float acc = 0.0f;
        #pragma unroll
        for (int k = 0; k < 4; k++) {
            float4 v = __ldcg(&rl4[threadIdx.x + k * 256]);  // L2-coherent read
            acc += (v.x + v.y) + (v.z + v.w);
        }
        float total = block_reduce_sum(acc);
        if (threadIdx.x == 0) {
            out[0] = total * (1.0f / (float)BATCH);
            g_done = 0;                          // reset for next graph replay
        }
    }
}

extern "C" void kernel_launch(void* const* d_in, const int* in_sizes, int n_in,
                              void* d_out, int out_size) {
    const float* logits  = (const float*)d_in[0];
    const int*   targets = (const int*)d_in[1];
    float*       out     = (float*)d_out;
    (void)in_sizes; (void)n_in; (void)out_size;

    stablemax_fused_kernel<<<BATCH, 256>>>(logits, targets, out);
}

// round 14
// speedup vs baseline: 1.1631x; 1.1136x over previous
#include <cuda_runtime.h>
#include <cuda_bf16.h>
#include <stdint.h>

#define BATCH 4096
#define NCLS  50257
#define EPSV  1e-12f

// Scratch + completion counter (no device allocation allowed -> __device__ globals)
__device__ float g_row_loss[BATCH];
__device__ unsigned int g_done = 0;

__device__ __forceinline__ float stable_s(float x) {
    // x >= 0 ? x + 1 : 1/(1-x)
    float p = x + 1.0f;
    float n = 1.0f - x;
    float r = __fdividef(1.0f, n);   // MUFU.RCP path (~1e-6 rel err)
    return (x >= 0.0f) ? p : r;
}

__device__ __forceinline__ float s4(float4 v) {
    return (stable_s(v.x) + stable_s(v.y)) + (stable_s(v.z) + stable_s(v.w));
}

__device__ __forceinline__ void prefetch_l2(const void* p) {
    asm volatile("prefetch.global.L2 [%0];" :: "l"(p));
}

// Re-entrant block reduction (leading barrier protects smem reuse across calls).
__device__ __forceinline__ float block_reduce_sum(float v) {
    __shared__ float warp_sums[8];
    int lane = threadIdx.x & 31;
    int wid  = threadIdx.x >> 5;
    __syncthreads();
    #pragma unroll
    for (int off = 16; off > 0; off >>= 1)
        v += __shfl_xor_sync(0xffffffffu, v, off);
    if (lane == 0) warp_sums[wid] = v;
    __syncthreads();
    v = (threadIdx.x < 8) ? warp_sums[threadIdx.x] : 0.0f;
    if (wid == 0) {
        #pragma unroll
        for (int off = 4; off > 0; off >>= 1)
            v += __shfl_xor_sync(0xffffffffu, v, off);
    }
    return v;  // valid in thread 0
}

__global__ void __launch_bounds__(256, 4)
stablemax_fused_kernel(const float* __restrict__ logits,
                       const int* __restrict__ targets,
                       float* __restrict__ out) {
    const int row = blockIdx.x;
    const float* __restrict__ rp = logits + (size_t)row * NCLS;
    const int stride = 256;

    // Hoist the target index load so its DRAM latency overlaps the main body.
    int tgt = 0;
    if (threadIdx.x == 0) {
        tgt = __ldg(&targets[row]);
        tgt = min(max(tgt, 0), NCLS - 1);   // fail-soft on dtype surprises
    }

    float acc0 = 0.f, acc1 = 0.f, acc2 = 0.f, acc3 = 0.f,
          acc4 = 0.f, acc5 = 0.f, acc6 = 0.f, acc7 = 0.f;

    // Scalar prefix until 16B alignment (row base only 4B aligned: NCLS odd)
    int prefix = (int)(((16u - ((uintptr_t)rp & 15u)) & 15u) >> 2);
    if (prefix > NCLS) prefix = NCLS;
    for (int j = threadIdx.x; j < prefix; j += stride)
        acc0 += stable_s(rp[j]);

    // 8x unrolled main body (measured optimum: 58 regs, 4 CTA/SM, DRAM 82.5%)
    // + register-free L2 prefetch of the NEXT batch issued before the compute
    // phase, so DRAM demand for batch k+1 overlaps consumption of batch k.
    const int n4 = (NCLS - prefix) >> 2;
    const float4* __restrict__ rp4 = (const float4*)(rp + prefix);
    int j = threadIdx.x;
    for (; j + 7 * stride < n4; j += 8 * stride) {
        float4 v0 = rp4[j];
        float4 v1 = rp4[j +     stride];
        float4 v2 = rp4[j + 2 * stride];
        float4 v3 = rp4[j + 3 * stride];
        float4 v4 = rp4[j + 4 * stride];
        float4 v5 = rp4[j + 5 * stride];
        float4 v6 = rp4[j + 6 * stride];
        float4 v7 = rp4[j + 7 * stride];
        // Prefetch next batch into L2 (no destination registers; in-bounds).
        if (j + 15 * stride < n4) {
            prefetch_l2(&rp4[j +  8 * stride]);
            prefetch_l2(&rp4[j +  9 * stride]);
            prefetch_l2(&rp4[j + 10 * stride]);
            prefetch_l2(&rp4[j + 11 * stride]);
            prefetch_l2(&rp4[j + 12 * stride]);
            prefetch_l2(&rp4[j + 13 * stride]);
            prefetch_l2(&rp4[j + 14 * stride]);
            prefetch_l2(&rp4[j + 15 * stride]);
        }
        acc0 += s4(v0);
        acc1 += s4(v1);
        acc2 += s4(v2);
        acc3 += s4(v3);
        acc4 += s4(v4);
        acc5 += s4(v5);
        acc6 += s4(v6);
        acc7 += s4(v7);
    }
    for (; j < n4; j += stride)
        acc0 += s4(rp4[j]);

    // Scalar tail (at most 3 elements)
    for (int t = prefix + (n4 << 2) + threadIdx.x; t < NCLS; t += stride)
        acc1 += stable_s(rp[t]);

    // Dependent target-logit load issued before the block reduction so its
    // latency hides under the barriers + shuffle tree.
    float st = 0.0f;
    if (threadIdx.x == 0)
        st = stable_s(__ldg(&rp[tgt]));

    float denom = block_reduce_sum(((acc0 + acc1) + (acc2 + acc3)) +
                                   ((acc4 + acc5) + (acc6 + acc7)));

    __shared__ bool is_last;
    if (threadIdx.x == 0) {
        denom = fmaxf(denom, EPSV);
        float pt = fmaxf(__fdividef(st, denom), EPSV);
        g_row_loss[row] = -__logf(pt);
        __threadfence();                         // publish row loss (release)
        unsigned int done = atomicAdd(&g_done, 1u);
        is_last = (done == (unsigned int)(BATCH - 1));
    }
    __syncthreads();

    if (is_last) {
        // Deterministic mean: fixed-order tree over g_row_loss.
        // 4096 floats = 1024 float4; 256 threads -> 4 float4 each, fixed indices.
        const float4* __restrict__ rl4 = (const float4*)g_row_loss;
        float acc = 0.0f;
        #pragma unroll
        for (int k = 0; k < 4; k++) {
            float4 v = __ldcg(&rl4[threadIdx.x + k * 256]);  // L2-coherent read
            acc += (v.x + v.y) + (v.z + v.w);
        }
        float total = block_reduce_sum(acc);
        if (threadIdx.x == 0) {
            out[0] = total * (1.0f / (float)BATCH);
            g_done = 0;                          // reset for next graph replay
        }
    }
}

extern "C" void kernel_launch(void* const* d_in, const int* in_sizes, int n_in,
                              void* d_out, int out_size) {
    const float* logits  = (const float*)d_in[0];
    const int*   targets = (const int*)d_in[1];
    float*       out     = (float*)d_out;
    (void)in_sizes; (void)n_in; (void)out_size;

    stablemax_fused_kernel<<<BATCH, 256>>>(logits, targets, out);
}